// round 17
// baseline (speedup 1.0000x reference)
#include <cuda_runtime.h>
#include <cuda_bf16.h>
#include <math.h>
#include <stdint.h>

// ============================================================================
// GCN decoder chain. Tensor-core GEMMs via mma.sync m16n8k16 bf16.
// R16 base + Round 17:
//  (a) adj-GEMMs z=16 -> z=14 (kseg 720): 1106 CTAs = exactly 4 waves of 296.
//  (b) syrk: dedicated 512-thread kernel, CTA tile 256x128 (two m-blocks
//      share one B tile; 25% less load traffic, prologue amortized), grid
//      (79,40) triangular early-exit, per-block direct/mirror store policy.
// NOTE: tcgen05 unavailable — harness ptxas targets sm_103 (no 'a').
// ============================================================================

#define NROWS 10000
#define ADJ_N 100000000LL
#define KTILE 64
#define SSTR 72                        // 64 k + 8 pad; conflict-free LDSM
#define ARR_BYTES (128 * SSTR * 2)     // 18432 per 128-row operand array
#define SMEM_NB2 (2 * 3 * ARR_BYTES)   // 110592: 2 stages x {A, BH, BL}
#define SMEM_SYRK (2 * 3 * ARR_BYTES)  // 110592: 2 stages x {A0, A1, B}

// ---------------- scratch (static __device__, allocation-free) -------------
__device__ __nv_bfloat16 g_adj_hi[100000000];
__device__ __nv_bfloat16 g_bt_hi[500 * 10000];
__device__ __nv_bfloat16 g_bt_lo[500 * 10000];
__device__ __nv_bfloat16 g_zh_hi[10000 * 512];   // pads (cols 500..511) stay 0
__device__ float g_f1[10000 * 512];
__device__ float g_f2[10000 * 512];
__device__ float g_part[40000000];               // split-K partials (160 MB)

// ---------------- helpers ----------------------------------------------------
__device__ __forceinline__ void split2(float x, __nv_bfloat16& h, __nv_bfloat16& l) {
    h = __float2bfloat16(x);
    l = __float2bfloat16(x - __bfloat162float(h));
}

__device__ __forceinline__ void cp16(uint32_t daddr, const void* src, int ok) {
    int sz = ok ? 16 : 0;
    asm volatile("cp.async.cg.shared.global [%0], [%1], 16, %2;"
                 :: "r"(daddr), "l"(src), "r"(sz));
}
__device__ __forceinline__ void cp_commit() {
    asm volatile("cp.async.commit_group;");
}
__device__ __forceinline__ void cp_wait1() {
    asm volatile("cp.async.wait_group 1;");
}
__device__ __forceinline__ void cp_wait0() {
    asm volatile("cp.async.wait_group 0;");
}
__device__ __forceinline__ void ldsm4(uint32_t& r0, uint32_t& r1, uint32_t& r2,
                                      uint32_t& r3, uint32_t addr) {
    asm volatile("ldmatrix.sync.aligned.m8n8.x4.shared.b16 {%0,%1,%2,%3}, [%4];"
                 : "=r"(r0), "=r"(r1), "=r"(r2), "=r"(r3) : "r"(addr));
}
__device__ __forceinline__ void mma16816(float c[4], const uint32_t a[4],
                                         const uint32_t b[2]) {
    asm volatile(
        "mma.sync.aligned.m16n8k16.row.col.f32.bf16.bf16.f32 "
        "{%0,%1,%2,%3}, {%4,%5,%6,%7}, {%8,%9}, {%0,%1,%2,%3};"
        : "+f"(c[0]), "+f"(c[1]), "+f"(c[2]), "+f"(c[3])
        : "r"(a[0]), "r"(a[1]), "r"(a[2]), "r"(a[3]), "r"(b[0]), "r"(b[1]));
}
__device__ __forceinline__ float fast_sigmoid(float x) {
    return __fdividef(1.0f, 1.0f + __expf(-x));
}

// ---------------- adj -> bf16 (hi only), float4 -----------------------------
__global__ void conv_vec4(const float* __restrict__ x,
                          __nv_bfloat16* __restrict__ hi, int n4)
{
    int i = blockIdx.x * blockDim.x + threadIdx.x;
    if (i >= n4) return;
    float4 v = reinterpret_cast<const float4*>(x)[i];
    reinterpret_cast<__nv_bfloat162*>(hi)[2 * i + 0] =
        __halves2bfloat162(__float2bfloat16(v.x), __float2bfloat16(v.y));
    reinterpret_cast<__nv_bfloat162*>(hi)[2 * i + 1] =
        __halves2bfloat162(__float2bfloat16(v.z), __float2bfloat16(v.w));
}

// ---------------- split-K partial reduce + activation ------------------------
template <int ACT, int S>
__global__ void reduce_act(const float* __restrict__ in, long long stride,
                           float* __restrict__ out, int n4)
{
    int i = blockIdx.x * blockDim.x + threadIdx.x;
    if (i >= n4) return;
    float4 a = reinterpret_cast<const float4*>(in)[i];
    #pragma unroll
    for (int p = 1; p < S; p++) {
        float4 b = reinterpret_cast<const float4*>(in + (long long)p * stride)[i];
        a.x += b.x; a.y += b.y; a.z += b.z; a.w += b.w;
    }
    if (ACT == 1) {
        a.x = tanhf(a.x); a.y = tanhf(a.y); a.z = tanhf(a.z); a.w = tanhf(a.w);
    }
    reinterpret_cast<float4*>(out)[i] = a;
}

// ---------------- transpose + split: T[Kt,Nn] fp32 -> hi/lo [Nn,Kt] bf16 ----
__global__ void tsplit_kernel(const float* __restrict__ T, int Kt, int Nn,
                              __nv_bfloat16* __restrict__ hi,
                              __nv_bfloat16* __restrict__ lo)
{
    __shared__ float sm[32][33];
    int tx = threadIdx.x & 31;
    int ty = threadIdx.x >> 5;
    int k0 = blockIdx.y * 32;
    int n0 = blockIdx.x * 32;
    #pragma unroll
    for (int r = 0; r < 4; r++) {
        int row = k0 + ty + r * 8;
        int col = n0 + tx;
        sm[ty + r * 8][tx] = (row < Kt && col < Nn) ? T[(size_t)row * Nn + col] : 0.0f;
    }
    __syncthreads();
    #pragma unroll
    for (int r = 0; r < 4; r++) {
        int n = n0 + ty + r * 8;
        int k = k0 + tx;
        if (n < Nn && k < Kt) {
            float v = sm[tx][ty + r * 8];
            __nv_bfloat16 h, l;
            split2(v, h, l);
            hi[(size_t)n * Kt + k] = h;
            lo[(size_t)n * Kt + k] = l;
        }
    }
}

// ---------------- 2-term tensor-core GEMM (adj layers) ----------------------
// C = A @ (BH+BL)^T; kseg split-K; partial -> C + z*M*ldc (no act).
__global__ __launch_bounds__(256, 2) void mma_gemm(
    const __nv_bfloat16* __restrict__ A, int lda,
    const __nv_bfloat16* __restrict__ Bhi, const __nv_bfloat16* __restrict__ Blo, int ldb,
    float* __restrict__ C, int ldc,
    int M, int N, int K, int kseg)
{
    extern __shared__ char smem[];
    constexpr int STAGE = 3 * ARR_BYTES;

    const int t    = threadIdx.x;
    const int lane = t & 31;
    const int wid  = t >> 5;
    const int wm   = (wid >> 2) * 64;
    const int wn   = (wid & 3) * 32;
    const int g    = lane >> 2;
    const int tg   = lane & 3;

    {
        int kb = blockIdx.z * kseg;
        A   += kb;
        Bhi += kb;
        Blo += kb;
        C += (size_t)blockIdx.z * M * ldc;
        K = min(K - kb, kseg);
    }

    const int m0 = blockIdx.y * 128;
    const int n0 = blockIdx.x * 128;

    float acc[4][4][4];
    #pragma unroll
    for (int i = 0; i < 4; i++)
        #pragma unroll
        for (int j = 0; j < 4; j++)
            #pragma unroll
            for (int c = 0; c < 4; c++) acc[i][j][c] = 0.0f;

    const int a_row = lane & 15;
    const int a_c8  = (lane >> 4) * 8;
    const int b_row = (lane & 7) + ((lane >> 4) << 3);
    const int b_c8  = ((lane >> 3) & 1) * 8;

    const int ntiles = (K + KTILE - 1) / KTILE;

    auto load_stage = [&](int s, int k0) {
        uint32_t base = (uint32_t)__cvta_generic_to_shared(smem) + s * STAGE;
        #pragma unroll
        for (int it = 0; it < 12; it++) {
            int idx = t + it * 256;
            int arr = idx >> 10;            // 0:A 1:BH 2:BL
            int rem = idx & 1023;
            int r   = rem >> 3;
            int c8  = (rem & 7) * 8;
            int gk  = k0 + c8;
            int kok = (gk < K);
            const __nv_bfloat16* src;
            int ok;
            if (arr == 0) {
                int ga = m0 + r;
                ok  = kok && (ga < M);
                src = A + (ok ? ((size_t)ga * lda + gk) : 0);
            } else {
                int gb = n0 + r;
                ok  = kok && (gb < N);
                src = (arr == 1 ? Bhi : Blo) + (ok ? ((size_t)gb * ldb + gk) : 0);
            }
            uint32_t so = (uint32_t)(r * SSTR + c8) * 2;
            cp16(base + (uint32_t)arr * ARR_BYTES + so, src, ok);
        }
    };

    load_stage(0, 0);
    cp_commit();

    int s = 0;
    for (int kt = 0; kt < ntiles; kt++) {
        __syncthreads();
        if (kt + 1 < ntiles) load_stage(s ^ 1, (kt + 1) * KTILE);
        cp_commit();
        cp_wait1();
        __syncthreads();

        const char* sb = smem + s * STAGE;
        const __nv_bfloat16* sA  = (const __nv_bfloat16*)(sb);
        const __nv_bfloat16* sBH = (const __nv_bfloat16*)(sb + 1 * ARR_BYTES);
        const __nv_bfloat16* sBL = (const __nv_bfloat16*)(sb + 2 * ARR_BYTES);

        #pragma unroll
        for (int ks = 0; ks < KTILE; ks += 16) {
            uint32_t ah[4][4], bh[2][4], bl[2][4];
            #pragma unroll
            for (int i = 0; i < 4; i++) {
                int off = (wm + i * 16 + a_row) * SSTR + ks + a_c8;
                ldsm4(ah[i][0], ah[i][1], ah[i][2], ah[i][3],
                      (uint32_t)__cvta_generic_to_shared(sA + off));
            }
            #pragma unroll
            for (int jp = 0; jp < 2; jp++) {
                int off = (wn + jp * 16 + b_row) * SSTR + ks + b_c8;
                ldsm4(bh[jp][0], bh[jp][1], bh[jp][2], bh[jp][3],
                      (uint32_t)__cvta_generic_to_shared(sBH + off));
                ldsm4(bl[jp][0], bl[jp][1], bl[jp][2], bl[jp][3],
                      (uint32_t)__cvta_generic_to_shared(sBL + off));
            }
            #pragma unroll
            for (int i = 0; i < 4; i++)
                #pragma unroll
                for (int j = 0; j < 4; j++)
                    mma16816(acc[i][j], ah[i], &bh[j >> 1][(j & 1) * 2]);
            #pragma unroll
            for (int i = 0; i < 4; i++)
                #pragma unroll
                for (int j = 0; j < 4; j++)
                    mma16816(acc[i][j], ah[i], &bl[j >> 1][(j & 1) * 2]);
        }
        s ^= 1;
    }

    // ---- epilogue (fp32 partial store) ----
    #pragma unroll
    for (int i = 0; i < 4; i++) {
        #pragma unroll
        for (int j = 0; j < 4; j++) {
            int cn = n0 + wn + j * 8 + 2 * tg;
            if (cn >= N) continue;
            #pragma unroll
            for (int h = 0; h < 2; h++) {
                int rm = m0 + wm + i * 16 + g + h * 8;
                if (rm >= M) continue;
                C[(size_t)rm * ldc + cn]     = acc[i][j][2 * h + 0];
                C[(size_t)rm * ldc + cn + 1] = acc[i][j][2 * h + 1];
            }
        }
    }
}

// ---------------- paired-block syrk: sigmoid(Z @ Z^T), triangular -----------
// CTA tile 256x128 (m-blocks i0=2*by, i0+1 share one B tile), 512 threads.
// Store policy per 128-block i vs column block bx: direct iff i >= bx,
// mirror iff i > bx (diagonal blocks direct-only; no duplicate writes).
__global__ __launch_bounds__(512, 1) void syrk_kernel(
    const __nv_bfloat16* __restrict__ Z, int ldz,
    float* __restrict__ C, int ldc, int Mtot, int K)
{
    extern __shared__ char smem[];
    constexpr int STAGE = 3 * ARR_BYTES;   // A0, A1, B

    const int bx = blockIdx.x;             // col 128-block, 0..78
    const int by = blockIdx.y;             // m-pair, 0..39
    if (2 * by + 1 < bx) return;           // fully above diagonal

    const int t    = threadIdx.x;
    const int lane = t & 31;
    const int wid  = t >> 5;               // 0..15
    const int wm   = (wid >> 2) * 64;      // 0,64,128,192
    const int wn   = (wid & 3) * 32;
    const int g    = lane >> 2;
    const int tg   = lane & 3;

    const int m0 = 256 * by;
    const int n0 = 128 * bx;

    float acc[4][4][4];
    #pragma unroll
    for (int i = 0; i < 4; i++)
        #pragma unroll
        for (int j = 0; j < 4; j++)
            #pragma unroll
            for (int c = 0; c < 4; c++) acc[i][j][c] = 0.0f;

    const int a_row = lane & 15;
    const int a_c8  = (lane >> 4) * 8;
    const int b_row = (lane & 7) + ((lane >> 4) << 3);
    const int b_c8  = ((lane >> 3) & 1) * 8;

    const int ntiles = K / KTILE;          // K=512 -> 8

    auto load_stage = [&](int s, int k0) {
        uint32_t base = (uint32_t)__cvta_generic_to_shared(smem) + s * STAGE;
        #pragma unroll
        for (int it = 0; it < 6; it++) {
            int idx = t + it * 512;         // 0..3071
            int arr = idx >> 10;            // 0,1: A halves; 2: B
            int rem = idx & 1023;
            int r   = rem >> 3;
            int c8  = (rem & 7) * 8;
            int gk  = k0 + c8;              // always < K
            int grow = (arr < 2) ? (m0 + arr * 128 + r) : (n0 + r);
            int ok   = (grow < Mtot);
            const __nv_bfloat16* src = Z + (ok ? ((size_t)grow * ldz + gk) : 0);
            uint32_t so = (uint32_t)(r * SSTR + c8) * 2;
            cp16(base + (uint32_t)arr * ARR_BYTES + so, src, ok);
        }
    };

    load_stage(0, 0);
    cp_commit();

    int s = 0;
    for (int kt = 0; kt < ntiles; kt++) {
        __syncthreads();
        if (kt + 1 < ntiles) load_stage(s ^ 1, (kt + 1) * KTILE);
        cp_commit();
        cp_wait1();
        __syncthreads();

        const char* sb = smem + s * STAGE;
        const __nv_bfloat16* sA = (const __nv_bfloat16*)(sb);          // 256 rows
        const __nv_bfloat16* sB = (const __nv_bfloat16*)(sb + 2 * ARR_BYTES);

        #pragma unroll
        for (int ks = 0; ks < KTILE; ks += 16) {
            uint32_t ah[4][4], bh[2][4];
            #pragma unroll
            for (int i = 0; i < 4; i++) {
                int off = (wm + i * 16 + a_row) * SSTR + ks + a_c8;
                ldsm4(ah[i][0], ah[i][1], ah[i][2], ah[i][3],
                      (uint32_t)__cvta_generic_to_shared(sA + off));
            }
            #pragma unroll
            for (int jp = 0; jp < 2; jp++) {
                int off = (wn + jp * 16 + b_row) * SSTR + ks + b_c8;
                ldsm4(bh[jp][0], bh[jp][1], bh[jp][2], bh[jp][3],
                      (uint32_t)__cvta_generic_to_shared(sB + off));
            }
            #pragma unroll
            for (int i = 0; i < 4; i++)
                #pragma unroll
                for (int j = 0; j < 4; j++)
                    mma16816(acc[i][j], ah[i], &bh[j >> 1][(j & 1) * 2]);
        }
        s ^= 1;
    }

    // my warp's 128-block
    const int myh = wm >> 7;               // 0 or 1
    const int myib = 2 * by + myh;
    const bool direct = (myib >= bx);

    // ---- direct stores (sigmoid) ----
    if (direct) {
        #pragma unroll
        for (int i = 0; i < 4; i++) {
            #pragma unroll
            for (int j = 0; j < 4; j++) {
                int cn = n0 + wn + j * 8 + 2 * tg;
                if (cn >= Mtot) continue;
                #pragma unroll
                for (int h8 = 0; h8 < 2; h8++) {
                    int rm = m0 + wm + i * 16 + g + h8 * 8;
                    if (rm >= Mtot) continue;
                    C[(size_t)rm * ldc + cn]     = fast_sigmoid(acc[i][j][2 * h8 + 0]);
                    C[(size_t)rm * ldc + cn + 1] = fast_sigmoid(acc[i][j][2 * h8 + 1]);
                }
            }
        }
    }

    // ---- mirror phases (one 128x132 tile, reused) ----
    float* tile = (float*)smem;
    cp_wait0();
    #pragma unroll
    for (int h = 0; h < 2; h++) {
        int ib = 2 * by + h;
        bool do_m = (ib > bx) && (m0 + h * 128 < Mtot);
        if (!do_m) continue;               // uniform across CTA
        __syncthreads();
        if (myh == h) {
            #pragma unroll
            for (int i = 0; i < 4; i++) {
                #pragma unroll
                for (int j = 0; j < 4; j++) {
                    int nl = wn + j * 8 + 2 * tg;
                    #pragma unroll
                    for (int h8 = 0; h8 < 2; h8++) {
                        int ml = (wm & 63) + ((wm >> 7) ? 0 : 0) + i * 16 + g + h8 * 8;
                        // local row within the 128-block: wm%128 + ...
                        int mloc = (wm & 127) + i * 16 + g + h8 * 8;
                        tile[(nl + 0) * 132 + mloc] = fast_sigmoid(acc[i][j][2 * h8 + 0]);
                        tile[(nl + 1) * 132 + mloc] = fast_sigmoid(acc[i][j][2 * h8 + 1]);
                        (void)ml;
                    }
                }
            }
        }
        __syncthreads();
        // write transpose block: C[n0+r][m0+h*128+c]
        for (int i = t; i < 128 * 32; i += 512) {
            int r  = i >> 5;
            int c4 = (i & 31) * 4;
            int gr = n0 + r;
            int gc = m0 + h * 128 + c4;
            if (gr < Mtot && gc < Mtot) {
                float4 v = *reinterpret_cast<const float4*>(&tile[r * 132 + c4]);
                *reinterpret_cast<float4*>(&C[(size_t)gr * ldc + gc]) = v;
            }
        }
    }
}

// ---------------- small fp32 SIMT GEMM (NN) for X @ W -----------------------
#define BM 128
#define BN 128
#define BK 8
template <int ACT, int WSP>
__global__ __launch_bounds__(256) void simt_gemm(
    const float* __restrict__ A, const float* __restrict__ B,
    float* __restrict__ C, int M, int N, int K,
    __nv_bfloat16* __restrict__ hi, int lds)
{
    __shared__ float As[BK][BM];
    __shared__ float Bs[BK][BN];
    const int t  = threadIdx.x;
    const int m0 = blockIdx.y * BM;
    const int n0 = blockIdx.x * BN;
    const int ar = t >> 1, ac = (t & 1) * 4;
    const int br = t >> 5, bc = (t & 31) * 4;
    const int ty = t >> 4, tx = t & 15;

    float acc[8][8];
    #pragma unroll
    for (int i = 0; i < 8; i++)
        #pragma unroll
        for (int j = 0; j < 8; j++) acc[i][j] = 0.0f;

    for (int k0 = 0; k0 < K; k0 += BK) {
        float4 av = make_float4(0.f, 0.f, 0.f, 0.f);
        if (m0 + ar < M && k0 + ac < K)
            av = *reinterpret_cast<const float4*>(A + (size_t)(m0 + ar) * K + k0 + ac);
        As[ac + 0][ar] = av.x; As[ac + 1][ar] = av.y;
        As[ac + 2][ar] = av.z; As[ac + 3][ar] = av.w;
        float4 bv = make_float4(0.f, 0.f, 0.f, 0.f);
        if (k0 + br < K && n0 + bc < N)
            bv = *reinterpret_cast<const float4*>(B + (size_t)(k0 + br) * N + n0 + bc);
        *reinterpret_cast<float4*>(&Bs[br][bc]) = bv;
        __syncthreads();
        #pragma unroll
        for (int kk = 0; kk < BK; kk++) {
            float a[8], b[8];
            *reinterpret_cast<float4*>(&a[0]) = *reinterpret_cast<const float4*>(&As[kk][ty * 8]);
            *reinterpret_cast<float4*>(&a[4]) = *reinterpret_cast<const float4*>(&As[kk][ty * 8 + 4]);
            *reinterpret_cast<float4*>(&b[0]) = *reinterpret_cast<const float4*>(&Bs[kk][tx * 8]);
            *reinterpret_cast<float4*>(&b[4]) = *reinterpret_cast<const float4*>(&Bs[kk][tx * 8 + 4]);
            #pragma unroll
            for (int i = 0; i < 8; i++)
                #pragma unroll
                for (int j = 0; j < 8; j++)
                    acc[i][j] = fmaf(a[i], b[j], acc[i][j]);
        }
        __syncthreads();
    }
    #pragma unroll
    for (int i = 0; i < 8; i++) {
        int m = m0 + ty * 8 + i;
        if (m >= M) continue;
        #pragma unroll
        for (int j = 0; j < 8; j++) {
            int n = n0 + tx * 8 + j;
            if (n < N) {
                float v = acc[i][j];
                if (ACT == 1) v = tanhf(v);
                C[(size_t)m * N + n] = v;
                if (WSP)
                    hi[(size_t)m * lds + n] = __float2bfloat16(v);
            }
        }
    }
}

// ---------------- driver -----------------------------------------------------
extern "C" void kernel_launch(void* const* d_in, const int* in_sizes, int n_in,
                              void* d_out, int out_size)
{
    const float* z_igae = (const float*)d_in[0];  // [10000, 20]
    const float* adj    = (const float*)d_in[1];  // [10000, 10000]
    const float* w3     = (const float*)d_in[2];  // [20, 256]
    const float* w4     = (const float*)d_in[3];  // [256, 128]
    const float* w5     = (const float*)d_in[4];  // [128, 500]

    float* out      = (float*)d_out;
    float* z_hat    = out;                          // [10000, 500]
    float* z_hatadj = out + (size_t)NROWS * 500;    // [10000, 10000]

    __nv_bfloat16 *adjH, *btH, *btL, *zhH;
    float *f1, *f2, *part;
    cudaGetSymbolAddress((void**)&adjH, g_adj_hi);
    cudaGetSymbolAddress((void**)&btH,  g_bt_hi);
    cudaGetSymbolAddress((void**)&btL,  g_bt_lo);
    cudaGetSymbolAddress((void**)&zhH,  g_zh_hi);
    cudaGetSymbolAddress((void**)&f1,   g_f1);
    cudaGetSymbolAddress((void**)&f2,   g_f2);
    cudaGetSymbolAddress((void**)&part, g_part);

    cudaFuncSetAttribute(mma_gemm,
                         cudaFuncAttributeMaxDynamicSharedMemorySize, SMEM_NB2);
    cudaFuncSetAttribute(syrk_kernel,
                         cudaFuncAttributeMaxDynamicSharedMemorySize, SMEM_SYRK);

    // 0. adj -> bf16 (hi only)
    {
        int n4 = (int)(ADJ_N / 4);
        conv_vec4<<<(n4 + 255) / 256, 256>>>(adj, adjH, n4);
    }

    dim3 blk(256);

    // 1. Z1 = tanh((adj @ z_igae) @ w3)  (R16 reorder).
    tsplit_kernel<<<dim3(1, 313), blk>>>(z_igae, NROWS, 20, btH, btL);
    mma_gemm<<<dim3(1, 79, 14), blk, SMEM_NB2>>>(
        adjH, NROWS, btH, btL, NROWS, part, 20, NROWS, 20, NROWS, 720);
    {
        int n4 = NROWS * 20 / 4;
        reduce_act<0, 14><<<(n4 + 255) / 256, blk>>>(
            part, (long long)NROWS * 20, f1, n4);
    }
    simt_gemm<1, 0><<<dim3(2, 79), blk>>>(f1, w3, f2, NROWS, 256, 20,
                                          nullptr, 0);
    // 2. T2 = Z1 @ w4  [10000,128]
    simt_gemm<0, 0><<<dim3(1, 79), blk>>>(f2, w4, f1, NROWS, 128, 256,
                                          nullptr, 0);
    // 3. transpose+split T2 -> [128,10000]
    tsplit_kernel<<<dim3(4, 313), blk>>>(f1, NROWS, 128, btH, btL);
    // 4. Z2 = tanh(adj @ T2): z=14 (4 exact waves), reduce+tanh -> f2
    mma_gemm<<<dim3(1, 79, 14), blk, SMEM_NB2>>>(
        adjH, NROWS, btH, btL, NROWS, part, 128, NROWS, 128, NROWS, 720);
    {
        int n4 = NROWS * 128 / 4;
        reduce_act<1, 14><<<(n4 + 255) / 256, blk>>>(
            part, (long long)NROWS * 128, f2, n4);
    }
    // 5. z_hat = (adj @ Z2) @ w5  (R14 reorder).
    tsplit_kernel<<<dim3(4, 313), blk>>>(f2, NROWS, 128, btH, btL);
    mma_gemm<<<dim3(1, 79, 14), blk, SMEM_NB2>>>(
        adjH, NROWS, btH, btL, NROWS, part, 128, NROWS, 128, NROWS, 720);
    {
        int n4 = NROWS * 128 / 4;
        reduce_act<0, 14><<<(n4 + 255) / 256, blk>>>(
            part, (long long)NROWS * 128, f1, n4);
    }
    simt_gemm<0, 1><<<dim3(4, 79), blk>>>(f1, w5, z_hat, NROWS, 500, 128,
                                          zhH, 512);
    // 6. z_hat_adj = sigmoid(zhH @ zhH^T): paired-block syrk, 512 threads
    syrk_kernel<<<dim3(79, 40), dim3(512), SMEM_SYRK>>>(
        zhH, 512, z_hatadj, NROWS, NROWS, 512);
}